// round 1
// baseline (speedup 1.0000x reference)
#include <cuda_runtime.h>
#include <math.h>
#include <stdint.h>

// ---------------------------------------------------------------------------
// ResidualDenoiser: x[8192,256] -> 3x (Linear->BN(eval)->ReLU->concat) -> Linear
//                   -> segmented softmax over ragged feature groups (10 segs).
//
// Activation buffer layout (width 3328): [ h2 (1024) | h1 (1024) | h0 (1024) | x (256) ]
//   layer0 in:  cols 3072..3327 (K= 256)   out: cols 2048..3071
//   layer1 in:  cols 2048..3327 (K=1280)   out: cols 1024..2047
//   layer2 in:  cols 1024..3327 (K=2304)   out: cols    0..1023
//   layer3 in:  cols    0..3327 (K=3328)   out: logits [8192,256]
// ---------------------------------------------------------------------------

#define B_ROWS 8192
#define ACT_W  3328
#define NSEG   10
#define EPS    1e-5f

__device__ float g_act[(size_t)B_ROWS * ACT_W];      // ~109 MB scratch
__device__ float g_logits[(size_t)B_ROWS * 256];     // ~8 MB

// ---------------------------------------------------------------------------
// Copy x into the tail columns of the activation buffer
// ---------------------------------------------------------------------------
__global__ void copy_x_kernel(const float* __restrict__ x) {
    int i = blockIdx.x * blockDim.x + threadIdx.x;   // over 8192*256
    int r = i >> 8;
    int c = i & 255;
    g_act[(size_t)r * ACT_W + 3072 + c] = x[i];
}

// ---------------------------------------------------------------------------
// Tiled SGEMM: C[r, f] = sum_k A[r, k] * W[f, k]  (+ bias, optional BN+ReLU)
// BM=128, BN=128, BK=16, 256 threads, 8x8 per-thread microtile.
// All dims are multiples of tiles (M=8192, N in {1024,256}, K mult of 16).
// ---------------------------------------------------------------------------
#define BM 128
#define BN 128
#define BK 16
#define TM 8
#define TN 8
#define PAD 4   // smem pad to reduce store bank conflicts

template <bool FUSE_BN_RELU>
__global__ __launch_bounds__(256, 2)
void gemm_kernel(const float* __restrict__ A, int lda,
                 const float* __restrict__ W,       // [Ntot, K] row-major
                 const float* __restrict__ bias,
                 const float* __restrict__ g, const float* __restrict__ be,
                 const float* __restrict__ rm, const float* __restrict__ rv,
                 float* __restrict__ C, int ldc,
                 int K)
{
    __shared__ float As[BK][BM + PAD];
    __shared__ float Bs[BK][BN + PAD];

    const int tid  = threadIdx.x;
    const int tx   = tid & 15;        // 16 col groups
    const int ty   = tid >> 4;        // 16 row groups
    const int row0 = blockIdx.y * BM;
    const int col0 = blockIdx.x * BN;

    float acc[TM][TN];
    #pragma unroll
    for (int i = 0; i < TM; i++)
        #pragma unroll
        for (int j = 0; j < TN; j++)
            acc[i][j] = 0.f;

    for (int k0 = 0; k0 < K; k0 += BK) {
        // --- load A tile (128 rows x 16 k) via float4, coalesced per 64B row chunk
        #pragma unroll
        for (int i = 0; i < 2; i++) {
            int idx = tid + i * 256;          // 512 float4 total
            int r   = idx >> 2;               // row within tile
            int kk4 = (idx & 3) << 2;         // k group
            float4 v = *reinterpret_cast<const float4*>(
                &A[(size_t)(row0 + r) * lda + k0 + kk4]);
            As[kk4 + 0][r] = v.x;
            As[kk4 + 1][r] = v.y;
            As[kk4 + 2][r] = v.z;
            As[kk4 + 3][r] = v.w;
        }
        // --- load W tile (128 cols x 16 k) via float4
        #pragma unroll
        for (int i = 0; i < 2; i++) {
            int idx = tid + i * 256;
            int c   = idx >> 2;
            int kk4 = (idx & 3) << 2;
            float4 v = *reinterpret_cast<const float4*>(
                &W[(size_t)(col0 + c) * K + k0 + kk4]);
            Bs[kk4 + 0][c] = v.x;
            Bs[kk4 + 1][c] = v.y;
            Bs[kk4 + 2][c] = v.z;
            Bs[kk4 + 3][c] = v.w;
        }
        __syncthreads();

        #pragma unroll
        for (int kk = 0; kk < BK; kk++) {
            float ra[TM], rb[TN];
            #pragma unroll
            for (int i = 0; i < TM; i++) ra[i] = As[kk][ty * TM + i];
            #pragma unroll
            for (int j = 0; j < TN; j++) rb[j] = Bs[kk][tx * TN + j];
            #pragma unroll
            for (int i = 0; i < TM; i++)
                #pragma unroll
                for (int j = 0; j < TN; j++)
                    acc[i][j] = fmaf(ra[i], rb[j], acc[i][j]);
        }
        __syncthreads();
    }

    // --- epilogue: +bias, optional BN(eval)+ReLU, store
    #pragma unroll
    for (int j = 0; j < TN; j++) {
        const int f = col0 + tx * TN + j;
        float bsum = bias[f];
        float scale = 1.f, shift = 0.f;
        if (FUSE_BN_RELU) {
            scale = g[f] * rsqrtf(rv[f] + EPS);
            shift = be[f] - rm[f] * scale;
        }
        #pragma unroll
        for (int i = 0; i < TM; i++) {
            const int r = row0 + ty * TM + i;
            float v = acc[i][j] + bsum;
            if (FUSE_BN_RELU) {
                v = fmaf(v, scale, shift);
                v = fmaxf(v, 0.f);
            }
            C[(size_t)r * ldc + f] = v;
        }
    }
}

// ---------------------------------------------------------------------------
// Segmented softmax over 256 features (10 ragged segments), one block per row.
// ---------------------------------------------------------------------------
__global__ void seg_softmax_kernel(const int* __restrict__ seg_ids,
                                   float* __restrict__ out)
{
    __shared__ float vals[256];
    __shared__ int   sseg[256];
    __shared__ float smax[NSEG];
    __shared__ float ssum[NSEG];

    const int row = blockIdx.x;
    const int t   = threadIdx.x;

    float v = g_logits[(size_t)row * 256 + t];   // TAU = 1.0
    vals[t] = v;
    sseg[t] = seg_ids[t];
    __syncthreads();

    if (t < NSEG) {
        float m = -3.402823466e+38f;
        for (int i = 0; i < 256; i++)
            if (sseg[i] == t) m = fmaxf(m, vals[i]);
        smax[t] = m;
    }
    __syncthreads();

    const int s = sseg[t];
    float e = expf(v - smax[s]);
    vals[t] = e;
    __syncthreads();

    if (t < NSEG) {
        float sum = 0.f;
        for (int i = 0; i < 256; i++)
            if (sseg[i] == t) sum += vals[i];
        ssum[t] = sum;
    }
    __syncthreads();

    out[(size_t)row * 256 + t] = e / ssum[s];
}

// ---------------------------------------------------------------------------
// Launch
// ---------------------------------------------------------------------------
extern "C" void kernel_launch(void* const* d_in, const int* in_sizes, int n_in,
                              void* d_out, int out_size)
{
    const float* x    = (const float*)d_in[0];
    const float* W0   = (const float*)d_in[1];
    const float* b0   = (const float*)d_in[2];
    const float* g0   = (const float*)d_in[3];
    const float* be0  = (const float*)d_in[4];
    const float* rm0  = (const float*)d_in[5];
    const float* rv0  = (const float*)d_in[6];
    const float* W1   = (const float*)d_in[7];
    const float* b1   = (const float*)d_in[8];
    const float* g1   = (const float*)d_in[9];
    const float* be1  = (const float*)d_in[10];
    const float* rm1  = (const float*)d_in[11];
    const float* rv1  = (const float*)d_in[12];
    const float* W2   = (const float*)d_in[13];
    const float* b2   = (const float*)d_in[14];
    const float* g2   = (const float*)d_in[15];
    const float* be2  = (const float*)d_in[16];
    const float* rm2  = (const float*)d_in[17];
    const float* rv2  = (const float*)d_in[18];
    const float* W3   = (const float*)d_in[19];
    const float* b3   = (const float*)d_in[20];
    const int*   seg  = (const int*)d_in[21];

    float* act    = nullptr;
    float* logits = nullptr;
    cudaGetSymbolAddress((void**)&act,    g_act);
    cudaGetSymbolAddress((void**)&logits, g_logits);

    // 1) copy x into activation buffer cols [3072, 3328)
    copy_x_kernel<<<(B_ROWS * 256) / 256, 256>>>(x);

    // 2) residual layers: GEMM + BN + ReLU (each writes its h block)
    dim3 blk(256);
    dim3 grid1024(1024 / BN, B_ROWS / BM);   // (8, 64)
    dim3 grid256(256 / BN, B_ROWS / BM);     // (2, 64)

    // layer 0: K=256, in at col 3072, out at col 2048
    gemm_kernel<true><<<grid1024, blk>>>(act + 3072, ACT_W, W0, b0, g0, be0, rm0, rv0,
                                         act + 2048, ACT_W, 256);
    // layer 1: K=1280, in at col 2048, out at col 1024
    gemm_kernel<true><<<grid1024, blk>>>(act + 2048, ACT_W, W1, b1, g1, be1, rm1, rv1,
                                         act + 1024, ACT_W, 1280);
    // layer 2: K=2304, in at col 1024, out at col 0
    gemm_kernel<true><<<grid1024, blk>>>(act + 1024, ACT_W, W2, b2, g2, be2, rm2, rv2,
                                         act + 0, ACT_W, 2304);
    // layer 3: K=3328, full input, out -> logits
    gemm_kernel<false><<<grid256, blk>>>(act, ACT_W, W3, b3,
                                         nullptr, nullptr, nullptr, nullptr,
                                         logits, 256, 3328);

    // 3) segmented softmax -> d_out
    seg_softmax_kernel<<<B_ROWS, 256>>>(seg, (float*)d_out);
}

// round 4
// speedup vs baseline: 2.3441x; 2.3441x over previous
#include <cuda_runtime.h>
#include <cuda_bf16.h>
#include <math.h>
#include <stdint.h>

// ---------------------------------------------------------------------------
// ResidualDenoiser via HMMA (mma.sync bf16, fp32 acc) with bf16 hi/lo split:
//   D = Ahi*Bhi + Ahi*Blo + Alo*Bhi   (rel err ~1e-5)
//
// Activation buffer (width 3328, bf16 hi + bf16 lo):
//   [ h2 (1024) | h1 (1024) | h0 (1024) | x (256) ]
// ---------------------------------------------------------------------------

#define B_ROWS 8192
#define ACT_W  3328
#define NSEG   10
#define EPS    1e-5f

#define TBM 128
#define TBN 128
#define KC  32
#define NSTAGE 3
#define ROWB 80                  // padded row stride (bytes) for 64B of k data
#define TILEB (128 * ROWB)       // 10240 bytes per tile
#define STAGEB (4 * TILEB)       // Ahi, Alo, Whi, Wlo
#define SMEM_BYTES (NSTAGE * STAGEB)

// weight hi/lo concat offsets
#define WOFF0 0
#define WOFF1 262144
#define WOFF2 1572864
#define WOFF3 3932160
#define WTOT  4784128

__device__ __nv_bfloat16 g_act_hi[(size_t)B_ROWS * ACT_W];
__device__ __nv_bfloat16 g_act_lo[(size_t)B_ROWS * ACT_W];
__device__ __nv_bfloat16 g_w_hi[WTOT];
__device__ __nv_bfloat16 g_w_lo[WTOT];
__device__ float         g_logits[(size_t)B_ROWS * 256];

__device__ __forceinline__ uint32_t smem_u32(const void* p) {
    uint32_t a;
    asm("{ .reg .u64 t; cvta.to.shared.u64 t, %1; cvt.u32.u64 %0, t; }" : "=r"(a) : "l"(p));
    return a;
}

#define CP_ASYNC16(dst, src) \
    asm volatile("cp.async.cg.shared.global [%0], [%1], 16;" :: "r"(dst), "l"(src))
#define CP_COMMIT()  asm volatile("cp.async.commit_group;" ::: "memory")
#define CP_WAIT2()   asm volatile("cp.async.wait_group 2;" ::: "memory")
#define CP_WAIT0()   asm volatile("cp.async.wait_group 0;" ::: "memory")

#define LDSM_X4(r0, r1, r2, r3, a) \
    asm volatile("ldmatrix.sync.aligned.m8n8.x4.shared.b16 {%0,%1,%2,%3}, [%4];" \
        : "=r"(r0), "=r"(r1), "=r"(r2), "=r"(r3) : "r"(a))

#define MMA_BF16(d, a, b) \
    asm volatile("mma.sync.aligned.m16n8k16.row.col.f32.bf16.bf16.f32 " \
        "{%0,%1,%2,%3}, {%4,%5,%6,%7}, {%8,%9}, {%0,%1,%2,%3};" \
        : "+f"((d)[0]), "+f"((d)[1]), "+f"((d)[2]), "+f"((d)[3]) \
        : "r"((a)[0]), "r"((a)[1]), "r"((a)[2]), "r"((a)[3]), \
          "r"((b)[0]), "r"((b)[1]))

// ---------------------------------------------------------------------------
// GEMM: C[r,f] = sum_k A[r,k]*W[f,k]
//   A hi/lo row stride ACT_W; W hi/lo row stride K.
//   BN=true : bias+BN+ReLU -> bf16 hi/lo out (row stride ACT_W)
//   BN=false: bias         -> fp32 out (row stride 256)
// ---------------------------------------------------------------------------
template <bool BN>
__global__ __launch_bounds__(256)
void mma_gemm(const __nv_bfloat16* __restrict__ Ahi, const __nv_bfloat16* __restrict__ Alo,
              const __nv_bfloat16* __restrict__ Whi, const __nv_bfloat16* __restrict__ Wlo,
              const float* __restrict__ bias,
              const float* __restrict__ gg, const float* __restrict__ be,
              const float* __restrict__ rm, const float* __restrict__ rv,
              __nv_bfloat16* __restrict__ Chi, __nv_bfloat16* __restrict__ Clo,
              float* __restrict__ Cf, int K)
{
    extern __shared__ char smem[];
    const uint32_t sbuf = smem_u32(smem);

    const int tid    = threadIdx.x;
    const int lane   = tid & 31;
    const int wid    = tid >> 5;
    const int warp_m = wid & 1;        // 2 warps over M (64 rows each)
    const int warp_n = wid >> 1;       // 4 warps over N (32 cols each)
    const int row0   = blockIdx.y * TBM;
    const int col0   = blockIdx.x * TBN;

    const int n_iter = K / KC;

    float acc[4][4][4];
    #pragma unroll
    for (int i = 0; i < 4; i++)
        #pragma unroll
        for (int j = 0; j < 4; j++)
            #pragma unroll
            for (int l = 0; l < 4; l++)
                acc[i][j][l] = 0.f;

    // per-thread cp.async coordinates: idx = tid + i*256, tile = i/2
    // r = (idx>>2)&127, c = idx&3 : 16B chunk c of row r
    const int ld_r = ((tid + 0) >> 2) & 63;   // recomputed per i below

    // stage loader
    auto load_stage = [&](int s) {
        const int k0  = s * KC;
        const uint32_t sb = sbuf + (s % NSTAGE) * STAGEB;
        #pragma unroll
        for (int i = 0; i < 8; i++) {
            const int idx  = tid + (i << 8);
            const int r    = (idx >> 2) & 127;
            const int c    = idx & 3;
            const uint32_t dst = sb + (i >> 1) * TILEB + r * ROWB + c * 16;
            const __nv_bfloat16* src;
            if (i < 2)      src = Ahi + (size_t)(row0 + r) * ACT_W + k0 + c * 8;
            else if (i < 4) src = Alo + (size_t)(row0 + r) * ACT_W + k0 + c * 8;
            else if (i < 6) src = Whi + (size_t)(col0 + r) * K     + k0 + c * 8;
            else            src = Wlo + (size_t)(col0 + r) * K     + k0 + c * 8;
            CP_ASYNC16(dst, src);
        }
    };
    (void)ld_r;

    // ldmatrix per-lane base offsets
    const uint32_t a_off = (uint32_t)((warp_m * 64 + (lane & 15)) * ROWB + (lane >> 4) * 16);
    const uint32_t b_off = (uint32_t)((warp_n * 32 + (lane >> 4) * 8 + (lane & 7)) * ROWB
                                      + ((lane >> 3) & 1) * 16);

    // prologue: stages 0,1
    load_stage(0); CP_COMMIT();
    load_stage(1); CP_COMMIT();

    for (int it = 0; it < n_iter; it++) {
        if (it + 2 < n_iter) load_stage(it + 2);
        CP_COMMIT();
        CP_WAIT2();
        __syncthreads();

        const uint32_t sb = sbuf + (it % NSTAGE) * STAGEB;
        #pragma unroll
        for (int kk = 0; kk < 2; kk++) {         // two k16 steps
            uint32_t ah[4][4], al[4][4], bh[4][2], bl[4][2];
            #pragma unroll
            for (int mt = 0; mt < 4; mt++) {
                const uint32_t aa = sb + a_off + mt * (16 * ROWB) + kk * 32;
                LDSM_X4(ah[mt][0], ah[mt][1], ah[mt][2], ah[mt][3], aa);
                LDSM_X4(al[mt][0], al[mt][1], al[mt][2], al[mt][3], aa + TILEB);
            }
            #pragma unroll
            for (int bt = 0; bt < 2; bt++) {
                const uint32_t ba = sb + 2 * TILEB + b_off + bt * (16 * ROWB) + kk * 32;
                uint32_t r0, r1, r2, r3;
                LDSM_X4(r0, r1, r2, r3, ba);
                bh[bt * 2][0] = r0; bh[bt * 2][1] = r1;
                bh[bt * 2 + 1][0] = r2; bh[bt * 2 + 1][1] = r3;
                LDSM_X4(r0, r1, r2, r3, ba + TILEB);
                bl[bt * 2][0] = r0; bl[bt * 2][1] = r1;
                bl[bt * 2 + 1][0] = r2; bl[bt * 2 + 1][1] = r3;
            }
            #pragma unroll
            for (int mt = 0; mt < 4; mt++)
                #pragma unroll
                for (int nt = 0; nt < 4; nt++) {
                    MMA_BF16(acc[mt][nt], ah[mt], bh[nt]);
                    MMA_BF16(acc[mt][nt], ah[mt], bl[nt]);
                    MMA_BF16(acc[mt][nt], al[mt], bh[nt]);
                }
        }
        __syncthreads();
    }
    CP_WAIT0();

    // ------------------------------ epilogue ------------------------------
    // c0,c1 -> row r, cols f,f+1 ; c2,c3 -> row r+8
    #pragma unroll
    for (int nt = 0; nt < 4; nt++) {
        const int f = col0 + warp_n * 32 + nt * 8 + (lane & 3) * 2;
        const float bs0 = bias[f], bs1 = bias[f + 1];
        float sc0 = 0.f, sh0 = 0.f, sc1 = 0.f, sh1 = 0.f;
        if (BN) {
            sc0 = gg[f]     * rsqrtf(rv[f]     + EPS);
            sc1 = gg[f + 1] * rsqrtf(rv[f + 1] + EPS);
            sh0 = be[f]     - rm[f]     * sc0;
            sh1 = be[f + 1] - rm[f + 1] * sc1;
        }
        #pragma unroll
        for (int mt = 0; mt < 4; mt++) {
            const int r = row0 + warp_m * 64 + mt * 16 + (lane >> 2);
            #pragma unroll
            for (int half = 0; half < 2; half++) {
                const int rr = r + half * 8;
                float v0 = acc[mt][nt][half * 2]     + bs0;
                float v1 = acc[mt][nt][half * 2 + 1] + bs1;
                if (BN) {
                    v0 = fmaxf(fmaf(v0, sc0, sh0), 0.f);
                    v1 = fmaxf(fmaf(v1, sc1, sh1), 0.f);
                    __nv_bfloat16 h0 = __float2bfloat16(v0);
                    __nv_bfloat16 h1 = __float2bfloat16(v1);
                    __nv_bfloat16 l0 = __float2bfloat16(v0 - __bfloat162float(h0));
                    __nv_bfloat16 l1 = __float2bfloat16(v1 - __bfloat162float(h1));
                    __nv_bfloat162 hp; hp.x = h0; hp.y = h1;
                    __nv_bfloat162 lp; lp.x = l0; lp.y = l1;
                    *reinterpret_cast<__nv_bfloat162*>(Chi + (size_t)rr * ACT_W + f) = hp;
                    *reinterpret_cast<__nv_bfloat162*>(Clo + (size_t)rr * ACT_W + f) = lp;
                } else {
                    float2 o; o.x = v0; o.y = v1;
                    *reinterpret_cast<float2*>(Cf + (size_t)rr * 256 + f) = o;
                }
            }
        }
    }
}

// ---------------------------------------------------------------------------
// hi/lo split conversions
// ---------------------------------------------------------------------------
__global__ void cvt_w_kernel(const float* __restrict__ src,
                             __nv_bfloat16* __restrict__ hi,
                             __nv_bfloat16* __restrict__ lo, int n)
{
    int i = blockIdx.x * blockDim.x + threadIdx.x;
    if (i < n) {
        float v = src[i];
        __nv_bfloat16 h = __float2bfloat16(v);
        hi[i] = h;
        lo[i] = __float2bfloat16(v - __bfloat162float(h));
    }
}

__global__ void cvt_x_kernel(const float* __restrict__ x)
{
    int i = blockIdx.x * blockDim.x + threadIdx.x;   // 8192*256
    int r = i >> 8;
    int c = i & 255;
    float v = x[i];
    __nv_bfloat16 h = __float2bfloat16(v);
    g_act_hi[(size_t)r * ACT_W + 3072 + c] = h;
    g_act_lo[(size_t)r * ACT_W + 3072 + c] = __float2bfloat16(v - __bfloat162float(h));
}

// ---------------------------------------------------------------------------
// Segmented softmax (one block per row)
// ---------------------------------------------------------------------------
__global__ void seg_softmax_kernel(const int* __restrict__ seg_ids,
                                   float* __restrict__ out)
{
    __shared__ float vals[256];
    __shared__ int   sseg[256];
    __shared__ float smax[NSEG];
    __shared__ float ssum[NSEG];

    const int row = blockIdx.x;
    const int t   = threadIdx.x;

    float v = g_logits[(size_t)row * 256 + t];
    vals[t] = v;
    sseg[t] = seg_ids[t];
    __syncthreads();

    if (t < NSEG) {
        float m = -3.402823466e+38f;
        for (int i = 0; i < 256; i++)
            if (sseg[i] == t) m = fmaxf(m, vals[i]);
        smax[t] = m;
    }
    __syncthreads();

    const int s = sseg[t];
    float e = expf(v - smax[s]);
    vals[t] = e;
    __syncthreads();

    if (t < NSEG) {
        float sum = 0.f;
        for (int i = 0; i < 256; i++)
            if (sseg[i] == t) sum += vals[i];
        ssum[t] = sum;
    }
    __syncthreads();

    out[(size_t)row * 256 + t] = e / ssum[s];
}

// ---------------------------------------------------------------------------
// Launch
// ---------------------------------------------------------------------------
extern "C" void kernel_launch(void* const* d_in, const int* in_sizes, int n_in,
                              void* d_out, int out_size)
{
    const float* x   = (const float*)d_in[0];
    const float* W0  = (const float*)d_in[1];
    const float* b0  = (const float*)d_in[2];
    const float* g0  = (const float*)d_in[3];
    const float* be0 = (const float*)d_in[4];
    const float* rm0 = (const float*)d_in[5];
    const float* rv0 = (const float*)d_in[6];
    const float* W1  = (const float*)d_in[7];
    const float* b1  = (const float*)d_in[8];
    const float* g1  = (const float*)d_in[9];
    const float* be1 = (const float*)d_in[10];
    const float* rm1 = (const float*)d_in[11];
    const float* rv1 = (const float*)d_in[12];
    const float* W2  = (const float*)d_in[13];
    const float* b2  = (const float*)d_in[14];
    const float* g2  = (const float*)d_in[15];
    const float* be2 = (const float*)d_in[16];
    const float* rm2 = (const float*)d_in[17];
    const float* rv2 = (const float*)d_in[18];
    const float* W3  = (const float*)d_in[19];
    const float* b3  = (const float*)d_in[20];
    const int*   seg = (const int*)d_in[21];

    __nv_bfloat16 *ah = nullptr, *al = nullptr, *wh = nullptr, *wl = nullptr;
    float* logits = nullptr;
    cudaGetSymbolAddress((void**)&ah, g_act_hi);
    cudaGetSymbolAddress((void**)&al, g_act_lo);
    cudaGetSymbolAddress((void**)&wh, g_w_hi);
    cudaGetSymbolAddress((void**)&wl, g_w_lo);
    cudaGetSymbolAddress((void**)&logits, g_logits);

    cudaFuncSetAttribute(mma_gemm<true>,  cudaFuncAttributeMaxDynamicSharedMemorySize, SMEM_BYTES);
    cudaFuncSetAttribute(mma_gemm<false>, cudaFuncAttributeMaxDynamicSharedMemorySize, SMEM_BYTES);

    // prologue: split conversions
    cvt_x_kernel<<<(B_ROWS * 256) / 256, 256>>>(x);
    cvt_w_kernel<<<(1024 * 256 + 255) / 256, 256>>>(W0, wh + WOFF0, wl + WOFF0, 1024 * 256);
    cvt_w_kernel<<<(1024 * 1280 + 255) / 256, 256>>>(W1, wh + WOFF1, wl + WOFF1, 1024 * 1280);
    cvt_w_kernel<<<(1024 * 2304 + 255) / 256, 256>>>(W2, wh + WOFF2, wl + WOFF2, 1024 * 2304);
    cvt_w_kernel<<<(256 * 3328 + 255) / 256, 256>>>(W3, wh + WOFF3, wl + WOFF3, 256 * 3328);

    dim3 blk(256);
    dim3 grid1024(1024 / TBN, B_ROWS / TBM);   // (8, 64)
    dim3 grid256(256 / TBN, B_ROWS / TBM);     // (2, 64)

    mma_gemm<true><<<grid1024, blk, SMEM_BYTES>>>(ah + 3072, al + 3072, wh + WOFF0, wl + WOFF0,
                                                  b0, g0, be0, rm0, rv0,
                                                  ah + 2048, al + 2048, nullptr, 256);
    mma_gemm<true><<<grid1024, blk, SMEM_BYTES>>>(ah + 2048, al + 2048, wh + WOFF1, wl + WOFF1,
                                                  b1, g1, be1, rm1, rv1,
                                                  ah + 1024, al + 1024, nullptr, 1280);
    mma_gemm<true><<<grid1024, blk, SMEM_BYTES>>>(ah + 1024, al + 1024, wh + WOFF2, wl + WOFF2,
                                                  b2, g2, be2, rm2, rv2,
                                                  ah, al, nullptr, 2304);
    mma_gemm<false><<<grid256, blk, SMEM_BYTES>>>(ah, al, wh + WOFF3, wl + WOFF3,
                                                  b3, nullptr, nullptr, nullptr, nullptr,
                                                  nullptr, nullptr, logits, 3328);

    seg_softmax_kernel<<<B_ROWS, 256>>>(seg, (float*)d_out);
}

// round 5
// speedup vs baseline: 3.1555x; 1.3461x over previous
#include <cuda_runtime.h>
#include <cuda_fp16.h>
#include <math.h>
#include <stdint.h>

// ---------------------------------------------------------------------------
// ResidualDenoiser via HMMA (mma.sync fp16, fp32 acc), 2-term split:
//   D = Ahi*Wh + Alo*Wh  (A exact as fp16 hi+lo, W quantized to fp16)
//   per-layer rel err ~2.8e-4 from W quantization only.
//
// Activation buffer (width 3328, fp16 hi + fp16 lo):
//   [ h2 (1024) | h1 (1024) | h0 (1024) | x (256) ]
// ---------------------------------------------------------------------------

#define B_ROWS 8192
#define ACT_W  3328
#define NSEG   10
#define EPS    1e-5f

#define TBM 128
#define TBN 128
#define KC  32
#define NSTAGE 4
#define ROWB 80                  // padded row stride (bytes) for 64B of k data
#define TILEB (128 * ROWB)       // 10240 bytes per tile
#define STAGEB (3 * TILEB)       // Ahi, Alo, Wh
#define SMEM_BYTES (NSTAGE * STAGEB)   // 122880

// weight concat offsets (elements)
#define WOFF0 0
#define WOFF1 262144
#define WOFF2 1572864
#define WOFF3 3932160
#define WTOT  4784128

__device__ __half g_act_hi[(size_t)B_ROWS * ACT_W];
__device__ __half g_act_lo[(size_t)B_ROWS * ACT_W];
__device__ __half g_w[WTOT];
__device__ float  g_logits[(size_t)B_ROWS * 256];

__device__ __forceinline__ uint32_t smem_u32(const void* p) {
    uint32_t a;
    asm("{ .reg .u64 t; cvta.to.shared.u64 t, %1; cvt.u32.u64 %0, t; }" : "=r"(a) : "l"(p));
    return a;
}

#define CP_ASYNC16(dst, src) \
    asm volatile("cp.async.cg.shared.global [%0], [%1], 16;" :: "r"(dst), "l"(src))
#define CP_COMMIT()  asm volatile("cp.async.commit_group;" ::: "memory")
#define CP_WAIT3()   asm volatile("cp.async.wait_group 3;" ::: "memory")
#define CP_WAIT0()   asm volatile("cp.async.wait_group 0;" ::: "memory")

#define LDSM_X4(r0, r1, r2, r3, a) \
    asm volatile("ldmatrix.sync.aligned.m8n8.x4.shared.b16 {%0,%1,%2,%3}, [%4];" \
        : "=r"(r0), "=r"(r1), "=r"(r2), "=r"(r3) : "r"(a))

#define MMA_F16(d, a, b) \
    asm volatile("mma.sync.aligned.m16n8k16.row.col.f32.f16.f16.f32 " \
        "{%0,%1,%2,%3}, {%4,%5,%6,%7}, {%8,%9}, {%0,%1,%2,%3};" \
        : "+f"((d)[0]), "+f"((d)[1]), "+f"((d)[2]), "+f"((d)[3]) \
        : "r"((a)[0]), "r"((a)[1]), "r"((a)[2]), "r"((a)[3]), \
          "r"((b)[0]), "r"((b)[1]))

// ---------------------------------------------------------------------------
// GEMM: C[r,f] = sum_k A[r,k]*W[f,k]
//   A hi/lo row stride ACT_W; W row stride K.
//   BN=true : bias+BN+ReLU -> fp16 hi/lo out (row stride ACT_W)
//   BN=false: bias         -> fp32 out (row stride 256)
// ---------------------------------------------------------------------------
template <bool BN>
__global__ __launch_bounds__(256)
void mma_gemm(const __half* __restrict__ Ahi, const __half* __restrict__ Alo,
              const __half* __restrict__ Wh,
              const float* __restrict__ bias,
              const float* __restrict__ gg, const float* __restrict__ be,
              const float* __restrict__ rm, const float* __restrict__ rv,
              __half* __restrict__ Chi, __half* __restrict__ Clo,
              float* __restrict__ Cf, int K)
{
    extern __shared__ char smem[];
    const uint32_t sbuf = smem_u32(smem);

    const int tid    = threadIdx.x;
    const int lane   = tid & 31;
    const int wid    = tid >> 5;
    const int warp_m = wid & 1;        // 2 warps over M (64 rows each)
    const int warp_n = wid >> 1;       // 4 warps over N (32 cols each)
    const int row0   = blockIdx.y * TBM;
    const int col0   = blockIdx.x * TBN;

    const int n_iter = K / KC;

    float acc[4][4][4];
    #pragma unroll
    for (int i = 0; i < 4; i++)
        #pragma unroll
        for (int j = 0; j < 4; j++)
            #pragma unroll
            for (int l = 0; l < 4; l++)
                acc[i][j][l] = 0.f;

    // stage loader: 3 tiles * 512 chunks of 16B = 1536 chunks = 6 x 256 threads
    auto load_stage = [&](int s) {
        const int k0  = s * KC;
        const uint32_t sb = sbuf + (s % NSTAGE) * STAGEB;
        #pragma unroll
        for (int i = 0; i < 6; i++) {
            const int idx  = tid + (i << 8);      // 0..1535
            const int t    = idx >> 9;            // tile 0..2
            const int w    = idx & 511;
            const int r    = w >> 2;              // row 0..127
            const int c    = w & 3;               // 16B chunk 0..3
            const uint32_t dst = sb + t * TILEB + r * ROWB + c * 16;
            const __half* src;
            if (t == 0)      src = Ahi + (size_t)(row0 + r) * ACT_W + k0 + c * 8;
            else if (t == 1) src = Alo + (size_t)(row0 + r) * ACT_W + k0 + c * 8;
            else             src = Wh  + (size_t)(col0 + r) * K     + k0 + c * 8;
            CP_ASYNC16(dst, src);
        }
    };

    // ldmatrix per-lane base offsets
    const uint32_t a_off = (uint32_t)((warp_m * 64 + (lane & 15)) * ROWB + (lane >> 4) * 16);
    const uint32_t b_off = (uint32_t)((warp_n * 32 + (lane >> 4) * 8 + (lane & 7)) * ROWB
                                      + ((lane >> 3) & 1) * 16);

    // prologue: stages 0,1,2
    load_stage(0); CP_COMMIT();
    load_stage(1); CP_COMMIT();
    load_stage(2); CP_COMMIT();

    for (int it = 0; it < n_iter; it++) {
        if (it + 3 < n_iter) load_stage(it + 3);
        CP_COMMIT();
        CP_WAIT3();
        __syncthreads();

        const uint32_t sb = sbuf + (it % NSTAGE) * STAGEB;
        #pragma unroll
        for (int kk = 0; kk < 2; kk++) {         // two k16 steps
            uint32_t ah[4][4], al[4][4], bh[4][2];
            #pragma unroll
            for (int mt = 0; mt < 4; mt++) {
                const uint32_t aa = sb + a_off + mt * (16 * ROWB) + kk * 32;
                LDSM_X4(ah[mt][0], ah[mt][1], ah[mt][2], ah[mt][3], aa);
                LDSM_X4(al[mt][0], al[mt][1], al[mt][2], al[mt][3], aa + TILEB);
            }
            #pragma unroll
            for (int bt = 0; bt < 2; bt++) {
                const uint32_t ba = sb + 2 * TILEB + b_off + bt * (16 * ROWB) + kk * 32;
                uint32_t r0, r1, r2, r3;
                LDSM_X4(r0, r1, r2, r3, ba);
                bh[bt * 2][0] = r0;     bh[bt * 2][1] = r1;
                bh[bt * 2 + 1][0] = r2; bh[bt * 2 + 1][1] = r3;
            }
            #pragma unroll
            for (int mt = 0; mt < 4; mt++)
                #pragma unroll
                for (int nt = 0; nt < 4; nt++) {
                    MMA_F16(acc[mt][nt], ah[mt], bh[nt]);
                    MMA_F16(acc[mt][nt], al[mt], bh[nt]);
                }
        }
        __syncthreads();
    }
    CP_WAIT0();

    // ------------------------------ epilogue ------------------------------
    #pragma unroll
    for (int nt = 0; nt < 4; nt++) {
        const int f = col0 + warp_n * 32 + nt * 8 + (lane & 3) * 2;
        const float bs0 = bias[f], bs1 = bias[f + 1];
        float sc0 = 0.f, sh0 = 0.f, sc1 = 0.f, sh1 = 0.f;
        if (BN) {
            sc0 = gg[f]     * rsqrtf(rv[f]     + EPS);
            sc1 = gg[f + 1] * rsqrtf(rv[f + 1] + EPS);
            sh0 = be[f]     - rm[f]     * sc0;
            sh1 = be[f + 1] - rm[f + 1] * sc1;
        }
        #pragma unroll
        for (int mt = 0; mt < 4; mt++) {
            const int r = row0 + warp_m * 64 + mt * 16 + (lane >> 2);
            #pragma unroll
            for (int half = 0; half < 2; half++) {
                const int rr = r + half * 8;
                float v0 = acc[mt][nt][half * 2]     + bs0;
                float v1 = acc[mt][nt][half * 2 + 1] + bs1;
                if (BN) {
                    v0 = fmaxf(fmaf(v0, sc0, sh0), 0.f);
                    v1 = fmaxf(fmaf(v1, sc1, sh1), 0.f);
                    __half h0 = __float2half(v0);
                    __half h1 = __float2half(v1);
                    __half l0 = __float2half(v0 - __half2float(h0));
                    __half l1 = __float2half(v1 - __half2float(h1));
                    __half2 hp; hp.x = h0; hp.y = h1;
                    __half2 lp; lp.x = l0; lp.y = l1;
                    *reinterpret_cast<__half2*>(Chi + (size_t)rr * ACT_W + f) = hp;
                    *reinterpret_cast<__half2*>(Clo + (size_t)rr * ACT_W + f) = lp;
                } else {
                    float2 o; o.x = v0; o.y = v1;
                    *reinterpret_cast<float2*>(Cf + (size_t)rr * 256 + f) = o;
                }
            }
        }
    }
}

// ---------------------------------------------------------------------------
// conversions
// ---------------------------------------------------------------------------
__global__ void cvt_w_kernel(const float* __restrict__ src,
                             __half* __restrict__ dst, int n)
{
    int i = blockIdx.x * blockDim.x + threadIdx.x;
    if (i < n) dst[i] = __float2half(src[i]);
}

__global__ void cvt_x_kernel(const float* __restrict__ x)
{
    int i = blockIdx.x * blockDim.x + threadIdx.x;   // 8192*256
    int r = i >> 8;
    int c = i & 255;
    float v = x[i];
    __half h = __float2half(v);
    g_act_hi[(size_t)r * ACT_W + 3072 + c] = h;
    g_act_lo[(size_t)r * ACT_W + 3072 + c] = __float2half(v - __half2float(h));
}

// ---------------------------------------------------------------------------
// Segmented softmax (one block per row)
// ---------------------------------------------------------------------------
__global__ void seg_softmax_kernel(const int* __restrict__ seg_ids,
                                   float* __restrict__ out)
{
    __shared__ float vals[256];
    __shared__ int   sseg[256];
    __shared__ float smax[NSEG];
    __shared__ float ssum[NSEG];

    const int row = blockIdx.x;
    const int t   = threadIdx.x;

    float v = g_logits[(size_t)row * 256 + t];
    vals[t] = v;
    sseg[t] = seg_ids[t];
    __syncthreads();

    if (t < NSEG) {
        float m = -3.402823466e+38f;
        for (int i = 0; i < 256; i++)
            if (sseg[i] == t) m = fmaxf(m, vals[i]);
        smax[t] = m;
    }
    __syncthreads();

    const int s = sseg[t];
    float e = expf(v - smax[s]);
    vals[t] = e;
    __syncthreads();

    if (t < NSEG) {
        float sum = 0.f;
        for (int i = 0; i < 256; i++)
            if (sseg[i] == t) sum += vals[i];
        ssum[t] = sum;
    }
    __syncthreads();

    out[(size_t)row * 256 + t] = e / ssum[s];
}

// ---------------------------------------------------------------------------
// Launch
// ---------------------------------------------------------------------------
extern "C" void kernel_launch(void* const* d_in, const int* in_sizes, int n_in,
                              void* d_out, int out_size)
{
    const float* x   = (const float*)d_in[0];
    const float* W0  = (const float*)d_in[1];
    const float* b0  = (const float*)d_in[2];
    const float* g0  = (const float*)d_in[3];
    const float* be0 = (const float*)d_in[4];
    const float* rm0 = (const float*)d_in[5];
    const float* rv0 = (const float*)d_in[6];
    const float* W1  = (const float*)d_in[7];
    const float* b1  = (const float*)d_in[8];
    const float* g1  = (const float*)d_in[9];
    const float* be1 = (const float*)d_in[10];
    const float* rm1 = (const float*)d_in[11];
    const float* rv1 = (const float*)d_in[12];
    const float* W2  = (const float*)d_in[13];
    const float* b2  = (const float*)d_in[14];
    const float* g2  = (const float*)d_in[15];
    const float* be2 = (const float*)d_in[16];
    const float* rm2 = (const float*)d_in[17];
    const float* rv2 = (const float*)d_in[18];
    const float* W3  = (const float*)d_in[19];
    const float* b3  = (const float*)d_in[20];
    const int*   seg = (const int*)d_in[21];

    __half *ah = nullptr, *al = nullptr, *wh = nullptr;
    float* logits = nullptr;
    cudaGetSymbolAddress((void**)&ah, g_act_hi);
    cudaGetSymbolAddress((void**)&al, g_act_lo);
    cudaGetSymbolAddress((void**)&wh, g_w);
    cudaGetSymbolAddress((void**)&logits, g_logits);

    cudaFuncSetAttribute(mma_gemm<true>,  cudaFuncAttributeMaxDynamicSharedMemorySize, SMEM_BYTES);
    cudaFuncSetAttribute(mma_gemm<false>, cudaFuncAttributeMaxDynamicSharedMemorySize, SMEM_BYTES);

    // prologue: conversions
    cvt_x_kernel<<<(B_ROWS * 256) / 256, 256>>>(x);
    cvt_w_kernel<<<(1024 * 256 + 255) / 256, 256>>>(W0, wh + WOFF0, 1024 * 256);
    cvt_w_kernel<<<(1024 * 1280 + 255) / 256, 256>>>(W1, wh + WOFF1, 1024 * 1280);
    cvt_w_kernel<<<(1024 * 2304 + 255) / 256, 256>>>(W2, wh + WOFF2, 1024 * 2304);
    cvt_w_kernel<<<(256 * 3328 + 255) / 256, 256>>>(W3, wh + WOFF3, 256 * 3328);

    dim3 blk(256);
    dim3 grid1024(1024 / TBN, B_ROWS / TBM);   // (8, 64)
    dim3 grid256(256 / TBN, B_ROWS / TBM);     // (2, 64)

    mma_gemm<true><<<grid1024, blk, SMEM_BYTES>>>(ah + 3072, al + 3072, wh + WOFF0,
                                                  b0, g0, be0, rm0, rv0,
                                                  ah + 2048, al + 2048, nullptr, 256);
    mma_gemm<true><<<grid1024, blk, SMEM_BYTES>>>(ah + 2048, al + 2048, wh + WOFF1,
                                                  b1, g1, be1, rm1, rv1,
                                                  ah + 1024, al + 1024, nullptr, 1280);
    mma_gemm<true><<<grid1024, blk, SMEM_BYTES>>>(ah + 1024, al + 1024, wh + WOFF2,
                                                  b2, g2, be2, rm2, rv2,
                                                  ah, al, nullptr, 2304);
    mma_gemm<false><<<grid256, blk, SMEM_BYTES>>>(ah, al, wh + WOFF3,
                                                  b3, nullptr, nullptr, nullptr, nullptr,
                                                  nullptr, nullptr, logits, 3328);

    seg_softmax_kernel<<<B_ROWS, 256>>>(seg, (float*)d_out);
}

// round 6
// speedup vs baseline: 5.6965x; 1.8053x over previous
#include <cuda_runtime.h>
#include <cuda_fp16.h>
#include <math.h>
#include <stdint.h>

// ---------------------------------------------------------------------------
// ResidualDenoiser via HMMA (mma.sync fp16, fp32 acc), pure fp16 inference:
//   D = fp16(A) * fp16(W), fp32 accumulate. rel err ~3e-4 (threshold 1e-3).
//
// Activation buffer (width 3328, fp16): [ h2 (1024) | h1 (1024) | h0 (1024) | x (256) ]
// ---------------------------------------------------------------------------

#define B_ROWS 8192
#define ACT_W  3328
#define NSEG   10
#define EPS    1e-5f

#define TBM 128
#define TBN 128
#define KC  32
#define NSTAGE 4
#define ROWB 80                  // padded row stride (bytes) for 64B of k data
#define TILEB (128 * ROWB)       // 10240 bytes per tile
#define STAGEB (2 * TILEB)       // A, W
#define SMEM_BYTES (NSTAGE * STAGEB)   // 81920

// weight concat offsets (elements)
#define WOFF0 0
#define WOFF1 262144
#define WOFF2 1572864
#define WOFF3 3932160
#define WTOT  4784128

__device__ __half g_act[(size_t)B_ROWS * ACT_W];
__device__ __half g_w[WTOT];
__device__ float  g_logits[(size_t)B_ROWS * 256];

__device__ __forceinline__ uint32_t smem_u32(const void* p) {
    uint32_t a;
    asm("{ .reg .u64 t; cvta.to.shared.u64 t, %1; cvt.u32.u64 %0, t; }" : "=r"(a) : "l"(p));
    return a;
}

#define CP_ASYNC16(dst, src) \
    asm volatile("cp.async.cg.shared.global [%0], [%1], 16;" :: "r"(dst), "l"(src))
#define CP_COMMIT()  asm volatile("cp.async.commit_group;" ::: "memory")
#define CP_WAIT3()   asm volatile("cp.async.wait_group 3;" ::: "memory")
#define CP_WAIT0()   asm volatile("cp.async.wait_group 0;" ::: "memory")

#define LDSM_X4(r0, r1, r2, r3, a) \
    asm volatile("ldmatrix.sync.aligned.m8n8.x4.shared.b16 {%0,%1,%2,%3}, [%4];" \
        : "=r"(r0), "=r"(r1), "=r"(r2), "=r"(r3) : "r"(a))

#define MMA_F16(d, a, b) \
    asm volatile("mma.sync.aligned.m16n8k16.row.col.f32.f16.f16.f32 " \
        "{%0,%1,%2,%3}, {%4,%5,%6,%7}, {%8,%9}, {%0,%1,%2,%3};" \
        : "+f"((d)[0]), "+f"((d)[1]), "+f"((d)[2]), "+f"((d)[3]) \
        : "r"((a)[0]), "r"((a)[1]), "r"((a)[2]), "r"((a)[3]), \
          "r"((b)[0]), "r"((b)[1]))

// ---------------------------------------------------------------------------
// GEMM: C[r,f] = sum_k A[r,k]*W[f,k]
//   A row stride ACT_W; W row stride K.
//   BN=true : bias+BN+ReLU -> fp16 out (row stride ACT_W)
//   BN=false: bias         -> fp32 out (row stride 256)
// ---------------------------------------------------------------------------
template <bool BN>
__global__ __launch_bounds__(256)
void mma_gemm(const __half* __restrict__ A,
              const __half* __restrict__ Wh,
              const float* __restrict__ bias,
              const float* __restrict__ gg, const float* __restrict__ be,
              const float* __restrict__ rm, const float* __restrict__ rv,
              __half* __restrict__ Ch,
              float* __restrict__ Cf, int K)
{
    extern __shared__ char smem[];
    const uint32_t sbuf = smem_u32(smem);

    const int tid    = threadIdx.x;
    const int lane   = tid & 31;
    const int wid    = tid >> 5;
    const int warp_m = wid & 1;        // 2 warps over M (64 rows each)
    const int warp_n = wid >> 1;       // 4 warps over N (32 cols each)
    const int row0   = blockIdx.y * TBM;
    const int col0   = blockIdx.x * TBN;

    const int n_iter = K / KC;

    float acc[4][4][4];
    #pragma unroll
    for (int i = 0; i < 4; i++)
        #pragma unroll
        for (int j = 0; j < 4; j++)
            #pragma unroll
            for (int l = 0; l < 4; l++)
                acc[i][j][l] = 0.f;

    // stage loader: 2 tiles * 512 chunks of 16B = 1024 chunks = 4 x 256 threads
    auto load_stage = [&](int s) {
        const int k0  = s * KC;
        const uint32_t sb = sbuf + (s % NSTAGE) * STAGEB;
        #pragma unroll
        for (int i = 0; i < 4; i++) {
            const int idx  = tid + (i << 8);      // 0..1023
            const int t    = idx >> 9;            // tile 0..1
            const int w    = idx & 511;
            const int r    = w >> 2;              // row 0..127
            const int c    = w & 3;               // 16B chunk 0..3
            const uint32_t dst = sb + t * TILEB + r * ROWB + c * 16;
            const __half* src;
            if (t == 0) src = A  + (size_t)(row0 + r) * ACT_W + k0 + c * 8;
            else        src = Wh + (size_t)(col0 + r) * K     + k0 + c * 8;
            CP_ASYNC16(dst, src);
        }
    };

    // ldmatrix per-lane base offsets
    const uint32_t a_off = (uint32_t)((warp_m * 64 + (lane & 15)) * ROWB + (lane >> 4) * 16);
    const uint32_t b_off = (uint32_t)((warp_n * 32 + (lane >> 4) * 8 + (lane & 7)) * ROWB
                                      + ((lane >> 3) & 1) * 16);

    // prologue: stages 0,1,2
    load_stage(0); CP_COMMIT();
    load_stage(1); CP_COMMIT();
    load_stage(2); CP_COMMIT();

    for (int it = 0; it < n_iter; it++) {
        if (it + 3 < n_iter) load_stage(it + 3);
        CP_COMMIT();
        CP_WAIT3();
        __syncthreads();

        const uint32_t sb = sbuf + (it % NSTAGE) * STAGEB;
        #pragma unroll
        for (int kk = 0; kk < 2; kk++) {         // two k16 steps
            uint32_t ah[4][4], bh[4][2];
            #pragma unroll
            for (int mt = 0; mt < 4; mt++) {
                const uint32_t aa = sb + a_off + mt * (16 * ROWB) + kk * 32;
                LDSM_X4(ah[mt][0], ah[mt][1], ah[mt][2], ah[mt][3], aa);
            }
            #pragma unroll
            for (int bt = 0; bt < 2; bt++) {
                const uint32_t ba = sb + TILEB + b_off + bt * (16 * ROWB) + kk * 32;
                uint32_t r0, r1, r2, r3;
                LDSM_X4(r0, r1, r2, r3, ba);
                bh[bt * 2][0] = r0;     bh[bt * 2][1] = r1;
                bh[bt * 2 + 1][0] = r2; bh[bt * 2 + 1][1] = r3;
            }
            #pragma unroll
            for (int mt = 0; mt < 4; mt++)
                #pragma unroll
                for (int nt = 0; nt < 4; nt++)
                    MMA_F16(acc[mt][nt], ah[mt], bh[nt]);
        }
        __syncthreads();
    }
    CP_WAIT0();

    // ------------------------------ epilogue ------------------------------
    #pragma unroll
    for (int nt = 0; nt < 4; nt++) {
        const int f = col0 + warp_n * 32 + nt * 8 + (lane & 3) * 2;
        const float bs0 = bias[f], bs1 = bias[f + 1];
        float sc0 = 0.f, sh0 = 0.f, sc1 = 0.f, sh1 = 0.f;
        if (BN) {
            sc0 = gg[f]     * rsqrtf(rv[f]     + EPS);
            sc1 = gg[f + 1] * rsqrtf(rv[f + 1] + EPS);
            sh0 = be[f]     - rm[f]     * sc0;
            sh1 = be[f + 1] - rm[f + 1] * sc1;
        }
        #pragma unroll
        for (int mt = 0; mt < 4; mt++) {
            const int r = row0 + warp_m * 64 + mt * 16 + (lane >> 2);
            #pragma unroll
            for (int half = 0; half < 2; half++) {
                const int rr = r + half * 8;
                float v0 = acc[mt][nt][half * 2]     + bs0;
                float v1 = acc[mt][nt][half * 2 + 1] + bs1;
                if (BN) {
                    v0 = fmaxf(fmaf(v0, sc0, sh0), 0.f);
                    v1 = fmaxf(fmaf(v1, sc1, sh1), 0.f);
                    __half2 hp; hp.x = __float2half(v0); hp.y = __float2half(v1);
                    *reinterpret_cast<__half2*>(Ch + (size_t)rr * ACT_W + f) = hp;
                } else {
                    float2 o; o.x = v0; o.y = v1;
                    *reinterpret_cast<float2*>(Cf + (size_t)rr * 256 + f) = o;
                }
            }
        }
    }
}

// ---------------------------------------------------------------------------
// conversions
// ---------------------------------------------------------------------------
__global__ void cvt_w_kernel(const float* __restrict__ src,
                             __half* __restrict__ dst, int n)
{
    int i = blockIdx.x * blockDim.x + threadIdx.x;
    if (i < n) dst[i] = __float2half(src[i]);
}

__global__ void cvt_x_kernel(const float* __restrict__ x)
{
    int i = blockIdx.x * blockDim.x + threadIdx.x;   // 8192*256
    int r = i >> 8;
    int c = i & 255;
    g_act[(size_t)r * ACT_W + 3072 + c] = __float2half(x[i]);
}

// ---------------------------------------------------------------------------
// Segmented softmax (one block per row)
// ---------------------------------------------------------------------------
__global__ void seg_softmax_kernel(const int* __restrict__ seg_ids,
                                   float* __restrict__ out)
{
    __shared__ float vals[256];
    __shared__ int   sseg[256];
    __shared__ float smax[NSEG];
    __shared__ float ssum[NSEG];

    const int row = blockIdx.x;
    const int t   = threadIdx.x;

    float v = g_logits[(size_t)row * 256 + t];
    vals[t] = v;
    sseg[t] = seg_ids[t];
    __syncthreads();

    if (t < NSEG) {
        float m = -3.402823466e+38f;
        for (int i = 0; i < 256; i++)
            if (sseg[i] == t) m = fmaxf(m, vals[i]);
        smax[t] = m;
    }
    __syncthreads();

    const int s = sseg[t];
    float e = expf(v - smax[s]);
    vals[t] = e;
    __syncthreads();

    if (t < NSEG) {
        float sum = 0.f;
        for (int i = 0; i < 256; i++)
            if (sseg[i] == t) sum += vals[i];
        ssum[t] = sum;
    }
    __syncthreads();

    out[(size_t)row * 256 + t] = e / ssum[s];
}

// ---------------------------------------------------------------------------
// Launch
// ---------------------------------------------------------------------------
extern "C" void kernel_launch(void* const* d_in, const int* in_sizes, int n_in,
                              void* d_out, int out_size)
{
    const float* x   = (const float*)d_in[0];
    const float* W0  = (const float*)d_in[1];
    const float* b0  = (const float*)d_in[2];
    const float* g0  = (const float*)d_in[3];
    const float* be0 = (const float*)d_in[4];
    const float* rm0 = (const float*)d_in[5];
    const float* rv0 = (const float*)d_in[6];
    const float* W1  = (const float*)d_in[7];
    const float* b1  = (const float*)d_in[8];
    const float* g1  = (const float*)d_in[9];
    const float* be1 = (const float*)d_in[10];
    const float* rm1 = (const float*)d_in[11];
    const float* rv1 = (const float*)d_in[12];
    const float* W2  = (const float*)d_in[13];
    const float* b2  = (const float*)d_in[14];
    const float* g2  = (const float*)d_in[15];
    const float* be2 = (const float*)d_in[16];
    const float* rm2 = (const float*)d_in[17];
    const float* rv2 = (const float*)d_in[18];
    const float* W3  = (const float*)d_in[19];
    const float* b3  = (const float*)d_in[20];
    const int*   seg = (const int*)d_in[21];

    __half *act = nullptr, *wh = nullptr;
    float* logits = nullptr;
    cudaGetSymbolAddress((void**)&act, g_act);
    cudaGetSymbolAddress((void**)&wh, g_w);
    cudaGetSymbolAddress((void**)&logits, g_logits);

    cudaFuncSetAttribute(mma_gemm<true>,  cudaFuncAttributeMaxDynamicSharedMemorySize, SMEM_BYTES);
    cudaFuncSetAttribute(mma_gemm<false>, cudaFuncAttributeMaxDynamicSharedMemorySize, SMEM_BYTES);

    // prologue: conversions
    cvt_x_kernel<<<(B_ROWS * 256) / 256, 256>>>(x);
    cvt_w_kernel<<<(1024 * 256 + 255) / 256, 256>>>(W0, wh + WOFF0, 1024 * 256);
    cvt_w_kernel<<<(1024 * 1280 + 255) / 256, 256>>>(W1, wh + WOFF1, 1024 * 1280);
    cvt_w_kernel<<<(1024 * 2304 + 255) / 256, 256>>>(W2, wh + WOFF2, 1024 * 2304);
    cvt_w_kernel<<<(256 * 3328 + 255) / 256, 256>>>(W3, wh + WOFF3, 256 * 3328);

    dim3 blk(256);
    dim3 grid1024(1024 / TBN, B_ROWS / TBM);   // (8, 64)
    dim3 grid256(256 / TBN, B_ROWS / TBM);     // (2, 64)

    mma_gemm<true><<<grid1024, blk, SMEM_BYTES>>>(act + 3072, wh + WOFF0,
                                                  b0, g0, be0, rm0, rv0,
                                                  act + 2048, nullptr, 256);
    mma_gemm<true><<<grid1024, blk, SMEM_BYTES>>>(act + 2048, wh + WOFF1,
                                                  b1, g1, be1, rm1, rv1,
                                                  act + 1024, nullptr, 1280);
    mma_gemm<true><<<grid1024, blk, SMEM_BYTES>>>(act + 1024, wh + WOFF2,
                                                  b2, g2, be2, rm2, rv2,
                                                  act, nullptr, 2304);
    mma_gemm<false><<<grid256, blk, SMEM_BYTES>>>(act, wh + WOFF3,
                                                  b3, nullptr, nullptr, nullptr, nullptr,
                                                  nullptr, logits, 3328);

    seg_softmax_kernel<<<B_ROWS, 256>>>(seg, (float*)d_out);
}